// round 13
// baseline (speedup 1.0000x reference)
#include <cuda_runtime.h>

#define Bsz 8
#define FD 1024
#define NN 65536
#define BNN (Bsz*NN)
#define Ksel 39321
#define M_TOT 2048

// ---------------- scratch ----------------
__device__ float    g_pp[M_TOT * 512];     // [m][0:256)=pr+b1, [256:512)=pc
__device__ float    g_e[BNN];
__device__ unsigned g_maxkey[Bsz];
__device__ float    g_inv_denom[Bsz];
__device__ float    g_part[Bsz * 64];
__device__ float    g_thr[Bsz];
__device__ float    g_cpart[Bsz * 64];
__device__ float    g_inv_csum[Bsz];

// monotone float<->uint encoding (for atomicMax over possibly-negative floats)
__device__ __forceinline__ unsigned encf(float f) {
    unsigned u = __float_as_uint(f);
    return (u & 0x80000000u) ? ~u : (u | 0x80000000u);
}
__device__ __forceinline__ float decf(unsigned u) {
    unsigned v = (u & 0x80000000u) ? (u ^ 0x80000000u) : ~u;
    return __uint_as_float(v);
}

__global__ void init_kernel() {
    if (threadIdx.x < Bsz) g_maxkey[threadIdx.x] = 0u;
}

// ---------------- 1) GEMM (R1 verbatim): C[m][j] = sum_f x[m][f]*Bmat[j][f] ----------------
__global__ __launch_bounds__(256) void gemm_kernel(
    const float* __restrict__ x, const float* __restrict__ W1, const float* __restrict__ b1)
{
    __shared__ float As[16][68];
    __shared__ float Bs[16][68];
    const int tid = threadIdx.x;
    const int m0 = blockIdx.y << 6;
    const int j0 = blockIdx.x << 6;
    const int tx = tid & 15, ty = tid >> 4;
    const int lr = tid >> 2;            // 0..63
    const int lc = (tid & 3) << 2;      // 0,4,8,12
    const int jrow = j0 + lr;
    const float* wrow = W1 + (jrow & 255) * 2048 + (jrow >> 8) * 1024;
    const float* arow = x + (m0 + lr) * 1024;
    float acc[4][4] = {};
    for (int k0 = 0; k0 < FD; k0 += 16) {
        float4 av = *(const float4*)(arow + k0 + lc);
        float4 bv = *(const float4*)(wrow + k0 + lc);
        __syncthreads();
        As[lc + 0][lr] = av.x; As[lc + 1][lr] = av.y; As[lc + 2][lr] = av.z; As[lc + 3][lr] = av.w;
        Bs[lc + 0][lr] = bv.x; Bs[lc + 1][lr] = bv.y; Bs[lc + 2][lr] = bv.z; Bs[lc + 3][lr] = bv.w;
        __syncthreads();
        #pragma unroll
        for (int k = 0; k < 16; k++) {
            float a[4], bb[4];
            *(float4*)a  = *(const float4*)&As[k][ty << 2];
            *(float4*)bb = *(const float4*)&Bs[k][tx << 2];
            #pragma unroll
            for (int i = 0; i < 4; i++)
                #pragma unroll
                for (int j = 0; j < 4; j++)
                    acc[i][j] = fmaf(a[i], bb[j], acc[i][j]);
        }
    }
    #pragma unroll
    for (int i = 0; i < 4; i++) {
        int m = m0 + (ty << 2) + i;
        #pragma unroll
        for (int j = 0; j < 4; j++) {
            int col = j0 + (tx << 2) + j;
            float v = acc[i][j];
            if (col < 256) v += b1[col];
            g_pp[m * 512 + col] = v;
        }
    }
}

// ---------------- 2) edge (R1 verbatim) ----------------
__global__ __launch_bounds__(256) void edge_kernel(
    const float* __restrict__ W2, const float* __restrict__ b2, float* __restrict__ out_edge)
{
    __shared__ float prs[64][33];
    __shared__ float pcs[64][33];
    __shared__ float w2s[32];
    __shared__ float redbuf[8];
    const int b  = blockIdx.z;
    const int i0 = blockIdx.y << 6;
    const int j0 = blockIdx.x << 6;
    const int tid = threadIdx.x;
    const int tx = tid & 15, ty = tid >> 4;
    const float* base = g_pp + (b << 8) * 512;
    float acc[4][4] = {};
    for (int hc = 0; hc < 256; hc += 32) {
        __syncthreads();
        #pragma unroll
        for (int t = 0; t < 2; t++) {
            int idx = tid + (t << 8);            // 0..511 float4 slots
            int r = idx >> 3;
            int hv = (idx & 7) << 2;
            float4 v = *(const float4*)(base + (i0 + r) * 512 + hc + hv);
            prs[r][hv] = v.x; prs[r][hv + 1] = v.y; prs[r][hv + 2] = v.z; prs[r][hv + 3] = v.w;
            float4 u = *(const float4*)(base + (j0 + r) * 512 + 256 + hc + hv);
            pcs[r][hv] = u.x; pcs[r][hv + 1] = u.y; pcs[r][hv + 2] = u.z; pcs[r][hv + 3] = u.w;
        }
        if (tid < 32) w2s[tid] = W2[hc + tid];
        __syncthreads();
        #pragma unroll
        for (int h = 0; h < 32; h++) {
            float w = w2s[h];
            float a[4], c[4];
            #pragma unroll
            for (int t = 0; t < 4; t++) { a[t] = prs[(ty << 2) + t][h]; c[t] = pcs[(tx << 2) + t][h]; }
            #pragma unroll
            for (int i = 0; i < 4; i++)
                #pragma unroll
                for (int j = 0; j < 4; j++) {
                    float v = a[i] + c[j];
                    v = fmaxf(v, 0.f);
                    acc[i][j] = fmaf(v, w, acc[i][j]);
                }
        }
    }
    float bb = b2[0];
    float lmax = -3.4e38f;
    #pragma unroll
    for (int i = 0; i < 4; i++) {
        int ii = i0 + (ty << 2) + i;
        #pragma unroll
        for (int j = 0; j < 4; j++) {
            int jj = j0 + (tx << 2) + j;
            float e = acc[i][j] + bb;
            out_edge[(b << 16) + (ii << 8) + jj] = e;
            lmax = fmaxf(lmax, e);
        }
    }
    #pragma unroll
    for (int o = 16; o > 0; o >>= 1) lmax = fmaxf(lmax, __shfl_xor_sync(0xffffffffu, lmax, o));
    if ((tid & 31) == 0) redbuf[tid >> 5] = lmax;
    __syncthreads();
    if (tid == 0) {
        float m = redbuf[0];
        #pragma unroll
        for (int i = 1; i < 8; i++) m = fmaxf(m, redbuf[i]);
        atomicMax(&g_maxkey[b], encf(m));
    }
}

// ---------------- 3) exp + partial sums (R1 verbatim) ----------------
__global__ __launch_bounds__(256) void exp_kernel(const float* __restrict__ edge)
{
    const int b = blockIdx.y;
    const int blk = blockIdx.x;     // 0..63
    const int tid = threadIdx.x;
    __shared__ float red[8];
    const float smax = 2.0f * decf(g_maxkey[b]);
    const int base = (b << 16) + (blk << 10);
    float s = 0.f;
    #pragma unroll
    for (int t = 0; t < 4; t++) {
        int idx = base + (t << 8) + tid;
        float e2 = __expf(fmaf(edge[idx], 2.0f, -smax));
        g_e[idx] = e2;
        s += e2;
    }
    #pragma unroll
    for (int o = 16; o > 0; o >>= 1) s += __shfl_xor_sync(0xffffffffu, s, o);
    if ((tid & 31) == 0) red[tid >> 5] = s;
    __syncthreads();
    if (tid == 0) {
        float tot = 0.f;
        #pragma unroll
        for (int i = 0; i < 8; i++) tot += red[i];
        g_part[(b << 6) + blk] = tot;
    }
}

__global__ void denom_kernel() {
    const int b = blockIdx.x, tid = threadIdx.x;   // 64 threads
    __shared__ float r2[2];
    float v = g_part[(b << 6) + tid];
    #pragma unroll
    for (int o = 16; o > 0; o >>= 1) v += __shfl_xor_sync(0xffffffffu, v, o);
    if ((tid & 31) == 0) r2[tid >> 5] = v;
    __syncthreads();
    if (tid == 0) g_inv_denom[b] = 1.0f / (r2[0] + r2[1]);
}

__global__ void soft_kernel(float* __restrict__ out_soft) {
    int idx = blockIdx.x * 256 + threadIdx.x;
    out_soft[idx] = g_e[idx] * g_inv_denom[idx >> 16];
}

// ---------------- 4) radix select: MLP-8 batched + warp-aggregated (THE one change) ----------------
__global__ __launch_bounds__(1024) void select_kernel(const float* __restrict__ soft)
{
    __shared__ unsigned hist[8][256];
    __shared__ unsigned sh_prefix;
    __shared__ int sh_rem;
    const int b = blockIdx.x;
    const int tid = threadIdx.x;
    const unsigned* keys = (const unsigned*)(soft + (b << 16));
    if (tid == 0) { sh_rem = Ksel; sh_prefix = 0u; }
    unsigned mask = 0u;
    for (int byte = 3; byte >= 0; byte--) {
        for (int i = tid; i < 2048; i += 1024) ((unsigned*)hist)[i] = 0u;
        __syncthreads();
        const unsigned prefix = sh_prefix;
        const int wg = (tid >> 5) & 7;
        const int sh = byte << 3;
        for (int t0 = tid; t0 < NN; t0 += 8192) {     // 8 outer iters, 8 batched LDGs each
            unsigned k[8];
            #pragma unroll
            for (int u = 0; u < 8; u++) k[u] = keys[t0 + u * 1024];
            #pragma unroll
            for (int u = 0; u < 8; u++) {
                bool act = (k[u] & mask) == prefix;
                unsigned bucket = (k[u] >> sh) & 255u;
                unsigned am = __ballot_sync(0xffffffffu, act);
                if (act) {
                    unsigned peers = __match_any_sync(am, bucket);
                    if ((unsigned)(__ffs(peers) - 1) == (tid & 31u))
                        atomicAdd(&hist[wg][bucket], __popc(peers));
                }
            }
        }
        __syncthreads();
        if (tid < 256) {
            unsigned s = 0;
            #pragma unroll
            for (int c = 0; c < 8; c++) s += hist[c][tid];
            hist[0][tid] = s;
        }
        __syncthreads();
        if (tid == 0) {
            int rem = sh_rem;
            unsigned cum = 0;
            int sel = 0;
            for (int bb = 255; bb >= 0; bb--) {
                unsigned c = hist[0][bb];
                if (cum + c >= (unsigned)rem) { sel = bb; sh_rem = rem - (int)cum; break; }
                cum += c;
            }
            sh_prefix = prefix | ((unsigned)sel << sh);
        }
        __syncthreads();
        mask |= (255u << sh);
    }
    if (tid == 0) g_thr[b] = __uint_as_float(sh_prefix);
}

// ---------------- 5) masked sum + final (R1 verbatim) ----------------
__global__ __launch_bounds__(256) void cmask_sum_kernel(const float* __restrict__ soft)
{
    const int b = blockIdx.y, blk = blockIdx.x, tid = threadIdx.x;
    __shared__ float red[8];
    const float thr = g_thr[b];
    const int base = (b << 16) + (blk << 10);
    float s = 0.f;
    #pragma unroll
    for (int t = 0; t < 4; t++) {
        float v = soft[base + (t << 8) + tid];
        if (v >= thr) s += v;
    }
    #pragma unroll
    for (int o = 16; o > 0; o >>= 1) s += __shfl_xor_sync(0xffffffffu, s, o);
    if ((tid & 31) == 0) red[tid >> 5] = s;
    __syncthreads();
    if (tid == 0) {
        float tot = 0.f;
        #pragma unroll
        for (int i = 0; i < 8; i++) tot += red[i];
        g_cpart[(b << 6) + blk] = tot;
    }
}

__global__ void csum_final_kernel() {
    const int b = blockIdx.x, tid = threadIdx.x;   // 64 threads
    __shared__ float r2[2];
    float v = g_cpart[(b << 6) + tid];
    #pragma unroll
    for (int o = 16; o > 0; o >>= 1) v += __shfl_xor_sync(0xffffffffu, v, o);
    if ((tid & 31) == 0) r2[tid >> 5] = v;
    __syncthreads();
    if (tid == 0) g_inv_csum[b] = 1.0f / (r2[0] + r2[1] + 1e-12f);
}

__global__ void final_kernel(const float* __restrict__ soft,
                             float* __restrict__ out_causal, float* __restrict__ out_conf)
{
    int idx = blockIdx.x * 256 + threadIdx.x;
    int b = idx >> 16;
    float v = soft[idx];
    float c = (v >= g_thr[b]) ? v * g_inv_csum[b] : 0.f;
    out_causal[idx] = c;
    out_conf[idx] = 1.f - c;
}

// ---------------- launch ----------------
// NOTE: two padding init launches so gemm_kernel sits at launch position 4,
// which is the slot ncu captures -> next round we see the GEMM's real profile.
extern "C" void kernel_launch(void* const* d_in, const int* in_sizes, int n_in,
                              void* d_out, int out_size)
{
    const float* x  = (const float*)d_in[0];
    const float* W1 = (const float*)d_in[1];
    const float* b1 = (const float*)d_in[2];
    const float* W2 = (const float*)d_in[3];
    const float* b2 = (const float*)d_in[4];
    float* out = (float*)d_out;
    float* out_causal = out;
    float* out_conf   = out + BNN;
    float* out_edge   = out + 2 * BNN;
    float* out_soft   = out + 3 * BNN;

    init_kernel<<<1, 32>>>();
    init_kernel<<<1, 32>>>();
    init_kernel<<<1, 32>>>();
    gemm_kernel<<<dim3(8, 32), 256>>>(x, W1, b1);   // launch #4 -> ncu target
    edge_kernel<<<dim3(4, 4, Bsz), 256>>>(W2, b2, out_edge);
    exp_kernel<<<dim3(64, Bsz), 256>>>(out_edge);
    denom_kernel<<<Bsz, 64>>>();
    soft_kernel<<<2048, 256>>>(out_soft);
    select_kernel<<<Bsz, 1024>>>(out_soft);
    cmask_sum_kernel<<<dim3(64, Bsz), 256>>>(out_soft);
    csum_final_kernel<<<Bsz, 64>>>();
    final_kernel<<<2048, 256>>>(out_soft, out_causal, out_conf);
}

// round 14
// speedup vs baseline: 1.2424x; 1.2424x over previous
#include <cuda_runtime.h>

#define Bsz 8
#define FD 1024
#define NN 65536
#define BNN (Bsz*NN)
#define Ksel 39321
#define M_TOT 2048

// ---------------- scratch ----------------
__device__ float    g_pp[M_TOT * 512];     // [m][0:256)=pr+b1, [256:512)=pc
__device__ float    g_e[BNN];
__device__ unsigned g_maxkey[Bsz];
__device__ float    g_inv_denom[Bsz];
__device__ float    g_part[Bsz * 64];
__device__ float    g_thr[Bsz];
__device__ float    g_cpart[Bsz * 64];
__device__ float    g_inv_csum[Bsz];

// monotone float<->uint encoding (for atomicMax over possibly-negative floats)
__device__ __forceinline__ unsigned encf(float f) {
    unsigned u = __float_as_uint(f);
    return (u & 0x80000000u) ? ~u : (u | 0x80000000u);
}
__device__ __forceinline__ float decf(unsigned u) {
    unsigned v = (u & 0x80000000u) ? (u ^ 0x80000000u) : ~u;
    return __uint_as_float(v);
}

__global__ void init_kernel() {
    if (threadIdx.x < Bsz) g_maxkey[threadIdx.x] = 0u;
}

// ---------------- 1) GEMM: broadcast-B layout ----------------
// C[m][j] = sum_f x[m][f]*Bmat[j][f]; Bmat[j][f] = W1[(j&255)][(j>>8)*1024+f].
// CTA = 64m x 32j, 256 threads = 8 warps; warp = 32 m-lanes x 8 j-cols
// (j warp-uniform -> B loads broadcast). Grid 16x32 = 512 CTAs.
// Per 4k per warp: 1 LDS.128 (A, conflict-free) + 8 broadcast LDS.128 (B)
// = 12 smem cyc vs 64 SMSP-cyc of FFMA -> FFMA-bound.
__global__ __launch_bounds__(256) void gemm_kernel(
    const float* __restrict__ x, const float* __restrict__ W1, const float* __restrict__ b1)
{
    __shared__ float As[64][36];   // [m][k], row stride 36 -> banks 4*m, conflict-free
    __shared__ float Bs[32][36];   // [k][j]
    const int tid = threadIdx.x;
    const int j0 = blockIdx.x << 5;     // 0..480
    const int m0 = blockIdx.y << 6;     // 0..1984
    const int lr = tid >> 3;            // 0..31 (A rows, B j-rows)
    const int lq = tid & 7;             // k-quad 0..7
    const int w = tid >> 5, lane = tid & 31;
    const int wm = w & 1, wj = w >> 1;  // warp m-half, j-group
    const int ml = (wm << 5) + lane;    // 0..63

    const float* arow0 = x + (m0 + lr) * 1024 + (lq << 2);
    const float* arow1 = x + (m0 + 32 + lr) * 1024 + (lq << 2);
    const int gj = j0 + lr;
    const float* brow = W1 + (gj & 255) * 2048 + (gj >> 8) * 1024 + (lq << 2);

    float acc[8] = {};

    float4 pa0 = *(const float4*)(arow0);
    float4 pa1 = *(const float4*)(arow1);
    float4 pb  = *(const float4*)(brow);

    for (int c = 0; c < 32; c++) {
        __syncthreads();
        *(float4*)&As[lr][lq << 2]      = pa0;
        *(float4*)&As[32 + lr][lq << 2] = pa1;
        Bs[(lq << 2) + 0][lr] = pb.x;
        Bs[(lq << 2) + 1][lr] = pb.y;
        Bs[(lq << 2) + 2][lr] = pb.z;
        Bs[(lq << 2) + 3][lr] = pb.w;
        __syncthreads();
        if (c < 31) {
            pa0 = *(const float4*)(arow0 + (c + 1) * 32);
            pa1 = *(const float4*)(arow1 + (c + 1) * 32);
            pb  = *(const float4*)(brow + (c + 1) * 32);
        }
        #pragma unroll
        for (int kk = 0; kk < 8; kk++) {
            float4 a4 = *(const float4*)&As[ml][kk << 2];
            float av[4] = {a4.x, a4.y, a4.z, a4.w};
            #pragma unroll
            for (int d = 0; d < 4; d++) {
                float4 blo = *(const float4*)&Bs[(kk << 2) + d][wj << 3];
                float4 bhi = *(const float4*)&Bs[(kk << 2) + d][(wj << 3) + 4];
                acc[0] = fmaf(av[d], blo.x, acc[0]);
                acc[1] = fmaf(av[d], blo.y, acc[1]);
                acc[2] = fmaf(av[d], blo.z, acc[2]);
                acc[3] = fmaf(av[d], blo.w, acc[3]);
                acc[4] = fmaf(av[d], bhi.x, acc[4]);
                acc[5] = fmaf(av[d], bhi.y, acc[5]);
                acc[6] = fmaf(av[d], bhi.z, acc[6]);
                acc[7] = fmaf(av[d], bhi.w, acc[7]);
            }
        }
    }
    // epilogue: fold b1 into cols < 256
    const int m = m0 + ml;
    const int colbase = j0 + (wj << 3);
    float out[8];
    #pragma unroll
    for (int jj = 0; jj < 8; jj++) {
        int col = colbase + jj;
        out[jj] = acc[jj] + ((col < 256) ? b1[col] : 0.f);
    }
    *(float4*)(g_pp + m * 512 + colbase)     = make_float4(out[0], out[1], out[2], out[3]);
    *(float4*)(g_pp + m * 512 + colbase + 4) = make_float4(out[4], out[5], out[6], out[7]);
}

// ---------------- 2) edge (R1 verbatim) ----------------
__global__ __launch_bounds__(256) void edge_kernel(
    const float* __restrict__ W2, const float* __restrict__ b2, float* __restrict__ out_edge)
{
    __shared__ float prs[64][33];
    __shared__ float pcs[64][33];
    __shared__ float w2s[32];
    __shared__ float redbuf[8];
    const int b  = blockIdx.z;
    const int i0 = blockIdx.y << 6;
    const int j0 = blockIdx.x << 6;
    const int tid = threadIdx.x;
    const int tx = tid & 15, ty = tid >> 4;
    const float* base = g_pp + (b << 8) * 512;
    float acc[4][4] = {};
    for (int hc = 0; hc < 256; hc += 32) {
        __syncthreads();
        #pragma unroll
        for (int t = 0; t < 2; t++) {
            int idx = tid + (t << 8);            // 0..511 float4 slots
            int r = idx >> 3;
            int hv = (idx & 7) << 2;
            float4 v = *(const float4*)(base + (i0 + r) * 512 + hc + hv);
            prs[r][hv] = v.x; prs[r][hv + 1] = v.y; prs[r][hv + 2] = v.z; prs[r][hv + 3] = v.w;
            float4 u = *(const float4*)(base + (j0 + r) * 512 + 256 + hc + hv);
            pcs[r][hv] = u.x; pcs[r][hv + 1] = u.y; pcs[r][hv + 2] = u.z; pcs[r][hv + 3] = u.w;
        }
        if (tid < 32) w2s[tid] = W2[hc + tid];
        __syncthreads();
        #pragma unroll
        for (int h = 0; h < 32; h++) {
            float w = w2s[h];
            float a[4], c[4];
            #pragma unroll
            for (int t = 0; t < 4; t++) { a[t] = prs[(ty << 2) + t][h]; c[t] = pcs[(tx << 2) + t][h]; }
            #pragma unroll
            for (int i = 0; i < 4; i++)
                #pragma unroll
                for (int j = 0; j < 4; j++) {
                    float v = a[i] + c[j];
                    v = fmaxf(v, 0.f);
                    acc[i][j] = fmaf(v, w, acc[i][j]);
                }
        }
    }
    float bb = b2[0];
    float lmax = -3.4e38f;
    #pragma unroll
    for (int i = 0; i < 4; i++) {
        int ii = i0 + (ty << 2) + i;
        #pragma unroll
        for (int j = 0; j < 4; j++) {
            int jj = j0 + (tx << 2) + j;
            float e = acc[i][j] + bb;
            out_edge[(b << 16) + (ii << 8) + jj] = e;
            lmax = fmaxf(lmax, e);
        }
    }
    #pragma unroll
    for (int o = 16; o > 0; o >>= 1) lmax = fmaxf(lmax, __shfl_xor_sync(0xffffffffu, lmax, o));
    if ((tid & 31) == 0) redbuf[tid >> 5] = lmax;
    __syncthreads();
    if (tid == 0) {
        float m = redbuf[0];
        #pragma unroll
        for (int i = 1; i < 8; i++) m = fmaxf(m, redbuf[i]);
        atomicMax(&g_maxkey[b], encf(m));
    }
}

// ---------------- 3) exp + partial sums (R1 verbatim) ----------------
__global__ __launch_bounds__(256) void exp_kernel(const float* __restrict__ edge)
{
    const int b = blockIdx.y;
    const int blk = blockIdx.x;     // 0..63
    const int tid = threadIdx.x;
    __shared__ float red[8];
    const float smax = 2.0f * decf(g_maxkey[b]);
    const int base = (b << 16) + (blk << 10);
    float s = 0.f;
    #pragma unroll
    for (int t = 0; t < 4; t++) {
        int idx = base + (t << 8) + tid;
        float e2 = __expf(fmaf(edge[idx], 2.0f, -smax));
        g_e[idx] = e2;
        s += e2;
    }
    #pragma unroll
    for (int o = 16; o > 0; o >>= 1) s += __shfl_xor_sync(0xffffffffu, s, o);
    if ((tid & 31) == 0) red[tid >> 5] = s;
    __syncthreads();
    if (tid == 0) {
        float tot = 0.f;
        #pragma unroll
        for (int i = 0; i < 8; i++) tot += red[i];
        g_part[(b << 6) + blk] = tot;
    }
}

__global__ void denom_kernel() {
    const int b = blockIdx.x, tid = threadIdx.x;   // 64 threads
    __shared__ float r2[2];
    float v = g_part[(b << 6) + tid];
    #pragma unroll
    for (int o = 16; o > 0; o >>= 1) v += __shfl_xor_sync(0xffffffffu, v, o);
    if ((tid & 31) == 0) r2[tid >> 5] = v;
    __syncthreads();
    if (tid == 0) g_inv_denom[b] = 1.0f / (r2[0] + r2[1]);
}

__global__ void soft_kernel(float* __restrict__ out_soft) {
    int idx = blockIdx.x * 256 + threadIdx.x;
    out_soft[idx] = g_e[idx] * g_inv_denom[idx >> 16];
}

// ---------------- 4) radix select (R1 plain version — match_any reverted) ----------------
__global__ __launch_bounds__(1024) void select_kernel(const float* __restrict__ soft)
{
    __shared__ unsigned hist[8][256];
    __shared__ unsigned sh_prefix;
    __shared__ int sh_rem;
    const int b = blockIdx.x;
    const int tid = threadIdx.x;
    const unsigned* keys = (const unsigned*)(soft + (b << 16));
    if (tid == 0) { sh_rem = Ksel; sh_prefix = 0u; }
    unsigned mask = 0u;
    for (int byte = 3; byte >= 0; byte--) {
        for (int i = tid; i < 2048; i += 1024) ((unsigned*)hist)[i] = 0u;
        __syncthreads();
        const unsigned prefix = sh_prefix;
        const int wg = (tid >> 5) & 7;
        const int sh = byte << 3;
        for (int t = tid; t < NN; t += 1024) {
            unsigned key = keys[t];
            if ((key & mask) == prefix)
                atomicAdd(&hist[wg][(key >> sh) & 255u], 1u);
        }
        __syncthreads();
        if (tid < 256) {
            unsigned s = 0;
            #pragma unroll
            for (int c = 0; c < 8; c++) s += hist[c][tid];
            hist[0][tid] = s;
        }
        __syncthreads();
        if (tid == 0) {
            int rem = sh_rem;
            unsigned cum = 0;
            int sel = 0;
            for (int bb = 255; bb >= 0; bb--) {
                unsigned c = hist[0][bb];
                if (cum + c >= (unsigned)rem) { sel = bb; sh_rem = rem - (int)cum; break; }
                cum += c;
            }
            sh_prefix = prefix | ((unsigned)sel << sh);
        }
        __syncthreads();
        mask |= (255u << sh);
    }
    if (tid == 0) g_thr[b] = __uint_as_float(sh_prefix);
}

// ---------------- 5) masked sum + final (R1 verbatim) ----------------
__global__ __launch_bounds__(256) void cmask_sum_kernel(const float* __restrict__ soft)
{
    const int b = blockIdx.y, blk = blockIdx.x, tid = threadIdx.x;
    __shared__ float red[8];
    const float thr = g_thr[b];
    const int base = (b << 16) + (blk << 10);
    float s = 0.f;
    #pragma unroll
    for (int t = 0; t < 4; t++) {
        float v = soft[base + (t << 8) + tid];
        if (v >= thr) s += v;
    }
    #pragma unroll
    for (int o = 16; o > 0; o >>= 1) s += __shfl_xor_sync(0xffffffffu, s, o);
    if ((tid & 31) == 0) red[tid >> 5] = s;
    __syncthreads();
    if (tid == 0) {
        float tot = 0.f;
        #pragma unroll
        for (int i = 0; i < 8; i++) tot += red[i];
        g_cpart[(b << 6) + blk] = tot;
    }
}

__global__ void csum_final_kernel() {
    const int b = blockIdx.x, tid = threadIdx.x;   // 64 threads
    __shared__ float r2[2];
    float v = g_cpart[(b << 6) + tid];
    #pragma unroll
    for (int o = 16; o > 0; o >>= 1) v += __shfl_xor_sync(0xffffffffu, v, o);
    if ((tid & 31) == 0) r2[tid >> 5] = v;
    __syncthreads();
    if (tid == 0) g_inv_csum[b] = 1.0f / (r2[0] + r2[1] + 1e-12f);
}

__global__ void final_kernel(const float* __restrict__ soft,
                             float* __restrict__ out_causal, float* __restrict__ out_conf)
{
    int idx = blockIdx.x * 256 + threadIdx.x;
    int b = idx >> 16;
    float v = soft[idx];
    float c = (v >= g_thr[b]) ? v * g_inv_csum[b] : 0.f;
    out_causal[idx] = c;
    out_conf[idx] = 1.f - c;
}

// ---------------- launch ----------------
// 3 init pads keep gemm_kernel at launch position 4 (the ncu-profiled slot).
extern "C" void kernel_launch(void* const* d_in, const int* in_sizes, int n_in,
                              void* d_out, int out_size)
{
    const float* x  = (const float*)d_in[0];
    const float* W1 = (const float*)d_in[1];
    const float* b1 = (const float*)d_in[2];
    const float* W2 = (const float*)d_in[3];
    const float* b2 = (const float*)d_in[4];
    float* out = (float*)d_out;
    float* out_causal = out;
    float* out_conf   = out + BNN;
    float* out_edge   = out + 2 * BNN;
    float* out_soft   = out + 3 * BNN;

    init_kernel<<<1, 32>>>();
    init_kernel<<<1, 32>>>();
    init_kernel<<<1, 32>>>();
    gemm_kernel<<<dim3(16, 32), 256>>>(x, W1, b1);   // launch #4 -> ncu target
    edge_kernel<<<dim3(4, 4, Bsz), 256>>>(W2, b2, out_edge);
    exp_kernel<<<dim3(64, Bsz), 256>>>(out_edge);
    denom_kernel<<<Bsz, 64>>>();
    soft_kernel<<<2048, 256>>>(out_soft);
    select_kernel<<<Bsz, 1024>>>(out_soft);
    cmask_sum_kernel<<<dim3(64, Bsz), 256>>>(out_soft);
    csum_final_kernel<<<Bsz, 64>>>();
    final_kernel<<<2048, 256>>>(out_soft, out_causal, out_conf);
}

// round 15
// speedup vs baseline: 1.2547x; 1.0100x over previous
#include <cuda_runtime.h>

#define Bsz 8
#define FD 1024
#define NN 65536
#define BNN (Bsz*NN)
#define Ksel 39321
#define M_TOT 2048

// ---------------- scratch ----------------
__device__ float    g_pp[M_TOT * 512];     // [m][0:256)=pr+b1, [256:512)=pc
__device__ float    g_e[BNN];
__device__ unsigned g_maxkey[Bsz];
__device__ float    g_inv_denom[Bsz];
__device__ float    g_part[Bsz * 64];
__device__ float    g_thr[Bsz];
__device__ float    g_cpart[Bsz * 64];
__device__ float    g_inv_csum[Bsz];

// monotone float<->uint encoding (for atomicMax over possibly-negative floats)
__device__ __forceinline__ unsigned encf(float f) {
    unsigned u = __float_as_uint(f);
    return (u & 0x80000000u) ? ~u : (u | 0x80000000u);
}
__device__ __forceinline__ float decf(unsigned u) {
    unsigned v = (u & 0x80000000u) ? (u ^ 0x80000000u) : ~u;
    return __uint_as_float(v);
}

__global__ void init_kernel() {
    if (threadIdx.x < Bsz) g_maxkey[threadIdx.x] = 0u;
}

// ---------------- 1) GEMM: broadcast-B + transposed conflict-free A ----------------
// C[m][j] = sum_f x[m][f]*Bmat[j][f]; Bmat[j][f] = W1[(j&255)][(j>>8)*1024+f].
// CTA = 64m x 32j, 256 threads = 8 warps; warp = 32 m-lanes x 8 j-cols (j warp-uniform).
// As[k][m] stride 65: reads (k+ml)%32 conflict-free LDS.32; writes (4lq+d+lr)%32 conflict-free.
// Bs reads are warp-uniform broadcasts (1 wf each).
// Per SM per 32k-chunk: 768 smem wf < 1024 FFMA cyc -> FFMA-bound.
__global__ __launch_bounds__(256) void gemm_kernel(
    const float* __restrict__ x, const float* __restrict__ W1, const float* __restrict__ b1)
{
    __shared__ float As[32][65];   // [k][m]
    __shared__ float Bs[32][36];   // [k][j]
    const int tid = threadIdx.x;
    const int j0 = blockIdx.x << 5;     // 0..480
    const int m0 = blockIdx.y << 6;     // 0..1984
    const int lr = tid >> 3;            // 0..31
    const int lq = tid & 7;             // k-quad 0..7
    const int w = tid >> 5, lane = tid & 31;
    const int wm = w & 1, wj = w >> 1;  // warp m-half, j-group
    const int ml = (wm << 5) + lane;    // 0..63

    const float* arow0 = x + (m0 + lr) * 1024 + (lq << 2);
    const float* arow1 = x + (m0 + 32 + lr) * 1024 + (lq << 2);
    const int gj = j0 + lr;
    const float* brow = W1 + (gj & 255) * 2048 + (gj >> 8) * 1024 + (lq << 2);

    float acc[8] = {};

    float4 pa0 = *(const float4*)(arow0);
    float4 pa1 = *(const float4*)(arow1);
    float4 pb  = *(const float4*)(brow);

    for (int c = 0; c < 32; c++) {
        __syncthreads();
        {
            const int kb = lq << 2;
            As[kb + 0][lr] = pa0.x; As[kb + 1][lr] = pa0.y;
            As[kb + 2][lr] = pa0.z; As[kb + 3][lr] = pa0.w;
            As[kb + 0][32 + lr] = pa1.x; As[kb + 1][32 + lr] = pa1.y;
            As[kb + 2][32 + lr] = pa1.z; As[kb + 3][32 + lr] = pa1.w;
            Bs[kb + 0][lr] = pb.x; Bs[kb + 1][lr] = pb.y;
            Bs[kb + 2][lr] = pb.z; Bs[kb + 3][lr] = pb.w;
        }
        __syncthreads();
        if (c < 31) {
            pa0 = *(const float4*)(arow0 + (c + 1) * 32);
            pa1 = *(const float4*)(arow1 + (c + 1) * 32);
            pb  = *(const float4*)(brow + (c + 1) * 32);
        }
        #pragma unroll
        for (int k = 0; k < 32; k++) {
            float a = As[k][ml];
            float4 blo = *(const float4*)&Bs[k][wj << 3];
            float4 bhi = *(const float4*)&Bs[k][(wj << 3) + 4];
            acc[0] = fmaf(a, blo.x, acc[0]);
            acc[1] = fmaf(a, blo.y, acc[1]);
            acc[2] = fmaf(a, blo.z, acc[2]);
            acc[3] = fmaf(a, blo.w, acc[3]);
            acc[4] = fmaf(a, bhi.x, acc[4]);
            acc[5] = fmaf(a, bhi.y, acc[5]);
            acc[6] = fmaf(a, bhi.z, acc[6]);
            acc[7] = fmaf(a, bhi.w, acc[7]);
        }
    }
    // epilogue: fold b1 into cols < 256
    const int m = m0 + ml;
    const int colbase = j0 + (wj << 3);
    float out[8];
    #pragma unroll
    for (int jj = 0; jj < 8; jj++) {
        int col = colbase + jj;
        out[jj] = acc[jj] + ((col < 256) ? b1[col] : 0.f);
    }
    *(float4*)(g_pp + m * 512 + colbase)     = make_float4(out[0], out[1], out[2], out[3]);
    *(float4*)(g_pp + m * 512 + colbase + 4) = make_float4(out[4], out[5], out[6], out[7]);
}

// ---------------- 2) edge (R1 verbatim) ----------------
__global__ __launch_bounds__(256) void edge_kernel(
    const float* __restrict__ W2, const float* __restrict__ b2, float* __restrict__ out_edge)
{
    __shared__ float prs[64][33];
    __shared__ float pcs[64][33];
    __shared__ float w2s[32];
    __shared__ float redbuf[8];
    const int b  = blockIdx.z;
    const int i0 = blockIdx.y << 6;
    const int j0 = blockIdx.x << 6;
    const int tid = threadIdx.x;
    const int tx = tid & 15, ty = tid >> 4;
    const float* base = g_pp + (b << 8) * 512;
    float acc[4][4] = {};
    for (int hc = 0; hc < 256; hc += 32) {
        __syncthreads();
        #pragma unroll
        for (int t = 0; t < 2; t++) {
            int idx = tid + (t << 8);            // 0..511 float4 slots
            int r = idx >> 3;
            int hv = (idx & 7) << 2;
            float4 v = *(const float4*)(base + (i0 + r) * 512 + hc + hv);
            prs[r][hv] = v.x; prs[r][hv + 1] = v.y; prs[r][hv + 2] = v.z; prs[r][hv + 3] = v.w;
            float4 u = *(const float4*)(base + (j0 + r) * 512 + 256 + hc + hv);
            pcs[r][hv] = u.x; pcs[r][hv + 1] = u.y; pcs[r][hv + 2] = u.z; pcs[r][hv + 3] = u.w;
        }
        if (tid < 32) w2s[tid] = W2[hc + tid];
        __syncthreads();
        #pragma unroll
        for (int h = 0; h < 32; h++) {
            float w = w2s[h];
            float a[4], c[4];
            #pragma unroll
            for (int t = 0; t < 4; t++) { a[t] = prs[(ty << 2) + t][h]; c[t] = pcs[(tx << 2) + t][h]; }
            #pragma unroll
            for (int i = 0; i < 4; i++)
                #pragma unroll
                for (int j = 0; j < 4; j++) {
                    float v = a[i] + c[j];
                    v = fmaxf(v, 0.f);
                    acc[i][j] = fmaf(v, w, acc[i][j]);
                }
        }
    }
    float bb = b2[0];
    float lmax = -3.4e38f;
    #pragma unroll
    for (int i = 0; i < 4; i++) {
        int ii = i0 + (ty << 2) + i;
        #pragma unroll
        for (int j = 0; j < 4; j++) {
            int jj = j0 + (tx << 2) + j;
            float e = acc[i][j] + bb;
            out_edge[(b << 16) + (ii << 8) + jj] = e;
            lmax = fmaxf(lmax, e);
        }
    }
    #pragma unroll
    for (int o = 16; o > 0; o >>= 1) lmax = fmaxf(lmax, __shfl_xor_sync(0xffffffffu, lmax, o));
    if ((tid & 31) == 0) redbuf[tid >> 5] = lmax;
    __syncthreads();
    if (tid == 0) {
        float m = redbuf[0];
        #pragma unroll
        for (int i = 1; i < 8; i++) m = fmaxf(m, redbuf[i]);
        atomicMax(&g_maxkey[b], encf(m));
    }
}

// ---------------- 3) exp + partial sums (R1 verbatim) ----------------
__global__ __launch_bounds__(256) void exp_kernel(const float* __restrict__ edge)
{
    const int b = blockIdx.y;
    const int blk = blockIdx.x;     // 0..63
    const int tid = threadIdx.x;
    __shared__ float red[8];
    const float smax = 2.0f * decf(g_maxkey[b]);
    const int base = (b << 16) + (blk << 10);
    float s = 0.f;
    #pragma unroll
    for (int t = 0; t < 4; t++) {
        int idx = base + (t << 8) + tid;
        float e2 = __expf(fmaf(edge[idx], 2.0f, -smax));
        g_e[idx] = e2;
        s += e2;
    }
    #pragma unroll
    for (int o = 16; o > 0; o >>= 1) s += __shfl_xor_sync(0xffffffffu, s, o);
    if ((tid & 31) == 0) red[tid >> 5] = s;
    __syncthreads();
    if (tid == 0) {
        float tot = 0.f;
        #pragma unroll
        for (int i = 0; i < 8; i++) tot += red[i];
        g_part[(b << 6) + blk] = tot;
    }
}

__global__ void denom_kernel() {
    const int b = blockIdx.x, tid = threadIdx.x;   // 64 threads
    __shared__ float r2[2];
    float v = g_part[(b << 6) + tid];
    #pragma unroll
    for (int o = 16; o > 0; o >>= 1) v += __shfl_xor_sync(0xffffffffu, v, o);
    if ((tid & 31) == 0) r2[tid >> 5] = v;
    __syncthreads();
    if (tid == 0) g_inv_denom[b] = 1.0f / (r2[0] + r2[1]);
}

__global__ void soft_kernel(float* __restrict__ out_soft) {
    int idx = blockIdx.x * 256 + threadIdx.x;
    out_soft[idx] = g_e[idx] * g_inv_denom[idx >> 16];
}

// ---------------- 4) radix select (R1 plain version) ----------------
__global__ __launch_bounds__(1024) void select_kernel(const float* __restrict__ soft)
{
    __shared__ unsigned hist[8][256];
    __shared__ unsigned sh_prefix;
    __shared__ int sh_rem;
    const int b = blockIdx.x;
    const int tid = threadIdx.x;
    const unsigned* keys = (const unsigned*)(soft + (b << 16));
    if (tid == 0) { sh_rem = Ksel; sh_prefix = 0u; }
    unsigned mask = 0u;
    for (int byte = 3; byte >= 0; byte--) {
        for (int i = tid; i < 2048; i += 1024) ((unsigned*)hist)[i] = 0u;
        __syncthreads();
        const unsigned prefix = sh_prefix;
        const int wg = (tid >> 5) & 7;
        const int sh = byte << 3;
        for (int t = tid; t < NN; t += 1024) {
            unsigned key = keys[t];
            if ((key & mask) == prefix)
                atomicAdd(&hist[wg][(key >> sh) & 255u], 1u);
        }
        __syncthreads();
        if (tid < 256) {
            unsigned s = 0;
            #pragma unroll
            for (int c = 0; c < 8; c++) s += hist[c][tid];
            hist[0][tid] = s;
        }
        __syncthreads();
        if (tid == 0) {
            int rem = sh_rem;
            unsigned cum = 0;
            int sel = 0;
            for (int bb = 255; bb >= 0; bb--) {
                unsigned c = hist[0][bb];
                if (cum + c >= (unsigned)rem) { sel = bb; sh_rem = rem - (int)cum; break; }
                cum += c;
            }
            sh_prefix = prefix | ((unsigned)sel << sh);
        }
        __syncthreads();
        mask |= (255u << sh);
    }
    if (tid == 0) g_thr[b] = __uint_as_float(sh_prefix);
}

// ---------------- 5) masked sum + final (R1 verbatim) ----------------
__global__ __launch_bounds__(256) void cmask_sum_kernel(const float* __restrict__ soft)
{
    const int b = blockIdx.y, blk = blockIdx.x, tid = threadIdx.x;
    __shared__ float red[8];
    const float thr = g_thr[b];
    const int base = (b << 16) + (blk << 10);
    float s = 0.f;
    #pragma unroll
    for (int t = 0; t < 4; t++) {
        float v = soft[base + (t << 8) + tid];
        if (v >= thr) s += v;
    }
    #pragma unroll
    for (int o = 16; o > 0; o >>= 1) s += __shfl_xor_sync(0xffffffffu, s, o);
    if ((tid & 31) == 0) red[tid >> 5] = s;
    __syncthreads();
    if (tid == 0) {
        float tot = 0.f;
        #pragma unroll
        for (int i = 0; i < 8; i++) tot += red[i];
        g_cpart[(b << 6) + blk] = tot;
    }
}

__global__ void csum_final_kernel() {
    const int b = blockIdx.x, tid = threadIdx.x;   // 64 threads
    __shared__ float r2[2];
    float v = g_cpart[(b << 6) + tid];
    #pragma unroll
    for (int o = 16; o > 0; o >>= 1) v += __shfl_xor_sync(0xffffffffu, v, o);
    if ((tid & 31) == 0) r2[tid >> 5] = v;
    __syncthreads();
    if (tid == 0) g_inv_csum[b] = 1.0f / (r2[0] + r2[1] + 1e-12f);
}

__global__ void final_kernel(const float* __restrict__ soft,
                             float* __restrict__ out_causal, float* __restrict__ out_conf)
{
    int idx = blockIdx.x * 256 + threadIdx.x;
    int b = idx >> 16;
    float v = soft[idx];
    float c = (v >= g_thr[b]) ? v * g_inv_csum[b] : 0.f;
    out_causal[idx] = c;
    out_conf[idx] = 1.f - c;
}

// ---------------- launch ----------------
// 3 init pads keep gemm_kernel at launch position 4 (the ncu-profiled slot).
extern "C" void kernel_launch(void* const* d_in, const int* in_sizes, int n_in,
                              void* d_out, int out_size)
{
    const float* x  = (const float*)d_in[0];
    const float* W1 = (const float*)d_in[1];
    const float* b1 = (const float*)d_in[2];
    const float* W2 = (const float*)d_in[3];
    const float* b2 = (const float*)d_in[4];
    float* out = (float*)d_out;
    float* out_causal = out;
    float* out_conf   = out + BNN;
    float* out_edge   = out + 2 * BNN;
    float* out_soft   = out + 3 * BNN;

    init_kernel<<<1, 32>>>();
    init_kernel<<<1, 32>>>();
    init_kernel<<<1, 32>>>();
    gemm_kernel<<<dim3(16, 32), 256>>>(x, W1, b1);   // launch #4 -> ncu target
    edge_kernel<<<dim3(4, 4, Bsz), 256>>>(W2, b2, out_edge);
    exp_kernel<<<dim3(64, Bsz), 256>>>(out_edge);
    denom_kernel<<<Bsz, 64>>>();
    soft_kernel<<<2048, 256>>>(out_soft);
    select_kernel<<<Bsz, 1024>>>(out_soft);
    cmask_sum_kernel<<<dim3(64, Bsz), 256>>>(out_soft);
    csum_final_kernel<<<Bsz, 64>>>();
    final_kernel<<<2048, 256>>>(out_soft, out_causal, out_conf);
}

// round 17
// speedup vs baseline: 1.5397x; 1.2271x over previous
#include <cuda_runtime.h>

#define Bsz 8
#define FD 1024
#define NN 65536
#define BNN (Bsz*NN)
#define Ksel 39321
#define M_TOT 2048

// ---------------- scratch ----------------
__device__ float    g_pp[M_TOT * 512];     // [m][0:256)=pr+b1, [256:512)=pc
__device__ float    g_e[BNN];
__device__ unsigned g_maxkey[Bsz];
__device__ float    g_inv_denom[Bsz];
__device__ float    g_part[Bsz * 64];
__device__ float    g_thr[Bsz];
__device__ float    g_cpart[Bsz * 64];
__device__ float    g_inv_csum[Bsz];

// monotone float<->uint encoding (for atomicMax over possibly-negative floats)
__device__ __forceinline__ unsigned encf(float f) {
    unsigned u = __float_as_uint(f);
    return (u & 0x80000000u) ? ~u : (u | 0x80000000u);
}
__device__ __forceinline__ float decf(unsigned u) {
    unsigned v = (u & 0x80000000u) ? (u ^ 0x80000000u) : ~u;
    return __uint_as_float(v);
}

__global__ void init_kernel() {
    if (threadIdx.x < Bsz) g_maxkey[threadIdx.x] = 0u;
}

// ---------------- 1) GEMM: 64x64 tile, 64 threads, 8x8/thread ----------------
// C[m][j] = sum_f x[m][f]*Bmat[j][f]; Bmat[j][f] = W1[(j&255)][(j>>8)*1024+f].
// Crossbar-byte model: per thread per k loads 64B (16 floats) for 64 FFMA
// -> 1 B/FFMA-lane < 2 B/FFMA budget -> FFMA-bound 2:1.
// Grid 8x32 = 256 CTAs, smem 8.7KB -> multiple CTAs/SM.
__global__ __launch_bounds__(64) void gemm_kernel(
    const float* __restrict__ x, const float* __restrict__ W1, const float* __restrict__ b1)
{
    __shared__ float As[16][68];   // [k][m]
    __shared__ float Bs[16][68];   // [k][j]
    const int tid = threadIdx.x;          // 0..63
    const int j0 = blockIdx.x << 6;
    const int m0 = blockIdx.y << 6;
    const int r  = tid >> 3;              // row group 0..7 -> rows 8r..8r+7
    const int cg = tid & 7;               // col group 0..7 -> cols 8cg..8cg+7

    // loader: A tile 64x16 = 256 float4; thread t handles f = t, t+64, t+128, t+192
    // f -> row = f>>2 (0..63), q = f&3 (k-quad)
    const float* xbase = x + m0 * 1024;
    // B rows are Bmat rows j0+row
    float acc[8][8] = {};

    float4 pa[4], pb[4];
    #pragma unroll
    for (int u = 0; u < 4; u++) {
        int f = tid + (u << 6);
        int row = f >> 2, q = f & 3;
        pa[u] = *(const float4*)(xbase + row * 1024 + (q << 2));
        int gj = j0 + row;
        pb[u] = *(const float4*)(W1 + (gj & 255) * 2048 + (gj >> 8) * 1024 + (q << 2));
    }

    for (int c = 0; c < 64; c++) {
        __syncthreads();
        #pragma unroll
        for (int u = 0; u < 4; u++) {
            int f = tid + (u << 6);
            int row = f >> 2, q = f & 3;
            As[(q << 2) + 0][row] = pa[u].x;
            As[(q << 2) + 1][row] = pa[u].y;
            As[(q << 2) + 2][row] = pa[u].z;
            As[(q << 2) + 3][row] = pa[u].w;
            Bs[(q << 2) + 0][row] = pb[u].x;
            Bs[(q << 2) + 1][row] = pb[u].y;
            Bs[(q << 2) + 2][row] = pb[u].z;
            Bs[(q << 2) + 3][row] = pb[u].w;
        }
        __syncthreads();
        if (c < 63) {
            const int k0 = (c + 1) << 4;
            #pragma unroll
            for (int u = 0; u < 4; u++) {
                int f = tid + (u << 6);
                int row = f >> 2, q = f & 3;
                pa[u] = *(const float4*)(xbase + row * 1024 + k0 + (q << 2));
                int gj = j0 + row;
                pb[u] = *(const float4*)(W1 + (gj & 255) * 2048 + (gj >> 8) * 1024 + k0 + (q << 2));
            }
        }
        #pragma unroll
        for (int k = 0; k < 16; k++) {
            float a[8], b[8];
            *(float4*)&a[0] = *(const float4*)&As[k][r << 3];
            *(float4*)&a[4] = *(const float4*)&As[k][(r << 3) + 4];
            *(float4*)&b[0] = *(const float4*)&Bs[k][cg << 3];
            *(float4*)&b[4] = *(const float4*)&Bs[k][(cg << 3) + 4];
            #pragma unroll
            for (int i = 0; i < 8; i++)
                #pragma unroll
                for (int j = 0; j < 8; j++)
                    acc[i][j] = fmaf(a[i], b[j], acc[i][j]);
        }
    }
    // epilogue: fold b1 into cols < 256
    const int colbase = j0 + (cg << 3);
    float bias[8];
    #pragma unroll
    for (int jj = 0; jj < 8; jj++) {
        int col = colbase + jj;
        bias[jj] = (col < 256) ? b1[col] : 0.f;
    }
    #pragma unroll
    for (int i = 0; i < 8; i++) {
        int m = m0 + (r << 3) + i;
        *(float4*)(g_pp + m * 512 + colbase) =
            make_float4(acc[i][0] + bias[0], acc[i][1] + bias[1],
                        acc[i][2] + bias[2], acc[i][3] + bias[3]);
        *(float4*)(g_pp + m * 512 + colbase + 4) =
            make_float4(acc[i][4] + bias[4], acc[i][5] + bias[5],
                        acc[i][6] + bias[6], acc[i][7] + bias[7]);
    }
}

// ---------------- 2) edge (R1 verbatim) ----------------
__global__ __launch_bounds__(256) void edge_kernel(
    const float* __restrict__ W2, const float* __restrict__ b2, float* __restrict__ out_edge)
{
    __shared__ float prs[64][33];
    __shared__ float pcs[64][33];
    __shared__ float w2s[32];
    __shared__ float redbuf[8];
    const int b  = blockIdx.z;
    const int i0 = blockIdx.y << 6;
    const int j0 = blockIdx.x << 6;
    const int tid = threadIdx.x;
    const int tx = tid & 15, ty = tid >> 4;
    const float* base = g_pp + (b << 8) * 512;
    float acc[4][4] = {};
    for (int hc = 0; hc < 256; hc += 32) {
        __syncthreads();
        #pragma unroll
        for (int t = 0; t < 2; t++) {
            int idx = tid + (t << 8);            // 0..511 float4 slots
            int r = idx >> 3;
            int hv = (idx & 7) << 2;
            float4 v = *(const float4*)(base + (i0 + r) * 512 + hc + hv);
            prs[r][hv] = v.x; prs[r][hv + 1] = v.y; prs[r][hv + 2] = v.z; prs[r][hv + 3] = v.w;
            float4 u = *(const float4*)(base + (j0 + r) * 512 + 256 + hc + hv);
            pcs[r][hv] = u.x; pcs[r][hv + 1] = u.y; pcs[r][hv + 2] = u.z; pcs[r][hv + 3] = u.w;
        }
        if (tid < 32) w2s[tid] = W2[hc + tid];
        __syncthreads();
        #pragma unroll
        for (int h = 0; h < 32; h++) {
            float w = w2s[h];
            float a[4], c[4];
            #pragma unroll
            for (int t = 0; t < 4; t++) { a[t] = prs[(ty << 2) + t][h]; c[t] = pcs[(tx << 2) + t][h]; }
            #pragma unroll
            for (int i = 0; i < 4; i++)
                #pragma unroll
                for (int j = 0; j < 4; j++) {
                    float v = a[i] + c[j];
                    v = fmaxf(v, 0.f);
                    acc[i][j] = fmaf(v, w, acc[i][j]);
                }
        }
    }
    float bb = b2[0];
    float lmax = -3.4e38f;
    #pragma unroll
    for (int i = 0; i < 4; i++) {
        int ii = i0 + (ty << 2) + i;
        #pragma unroll
        for (int j = 0; j < 4; j++) {
            int jj = j0 + (tx << 2) + j;
            float e = acc[i][j] + bb;
            out_edge[(b << 16) + (ii << 8) + jj] = e;
            lmax = fmaxf(lmax, e);
        }
    }
    #pragma unroll
    for (int o = 16; o > 0; o >>= 1) lmax = fmaxf(lmax, __shfl_xor_sync(0xffffffffu, lmax, o));
    if ((tid & 31) == 0) redbuf[tid >> 5] = lmax;
    __syncthreads();
    if (tid == 0) {
        float m = redbuf[0];
        #pragma unroll
        for (int i = 1; i < 8; i++) m = fmaxf(m, redbuf[i]);
        atomicMax(&g_maxkey[b], encf(m));
    }
}

// ---------------- 3) exp + partial sums (R1 verbatim) ----------------
__global__ __launch_bounds__(256) void exp_kernel(const float* __restrict__ edge)
{
    const int b = blockIdx.y;
    const int blk = blockIdx.x;     // 0..63
    const int tid = threadIdx.x;
    __shared__ float red[8];
    const float smax = 2.0f * decf(g_maxkey[b]);
    const int base = (b << 16) + (blk << 10);
    float s = 0.f;
    #pragma unroll
    for (int t = 0; t < 4; t++) {
        int idx = base + (t << 8) + tid;
        float e2 = __expf(fmaf(edge[idx], 2.0f, -smax));
        g_e[idx] = e2;
        s += e2;
    }
    #pragma unroll
    for (int o = 16; o > 0; o >>= 1) s += __shfl_xor_sync(0xffffffffu, s, o);
    if ((tid & 31) == 0) red[tid >> 5] = s;
    __syncthreads();
    if (tid == 0) {
        float tot = 0.f;
        #pragma unroll
        for (int i = 0; i < 8; i++) tot += red[i];
        g_part[(b << 6) + blk] = tot;
    }
}

__global__ void denom_kernel() {
    const int b = blockIdx.x, tid = threadIdx.x;   // 64 threads
    __shared__ float r2[2];
    float v = g_part[(b << 6) + tid];
    #pragma unroll
    for (int o = 16; o > 0; o >>= 1) v += __shfl_xor_sync(0xffffffffu, v, o);
    if ((tid & 31) == 0) r2[tid >> 5] = v;
    __syncthreads();
    if (tid == 0) g_inv_denom[b] = 1.0f / (r2[0] + r2[1]);
}

__global__ void soft_kernel(float* __restrict__ out_soft) {
    int idx = blockIdx.x * 256 + threadIdx.x;
    out_soft[idx] = g_e[idx] * g_inv_denom[idx >> 16];
}

// ---------------- 4) radix select (R1 plain version) ----------------
__global__ __launch_bounds__(1024) void select_kernel(const float* __restrict__ soft)
{
    __shared__ unsigned hist[8][256];
    __shared__ unsigned sh_prefix;
    __shared__ int sh_rem;
    const int b = blockIdx.x;
    const int tid = threadIdx.x;
    const unsigned* keys = (const unsigned*)(soft + (b << 16));
    if (tid == 0) { sh_rem = Ksel; sh_prefix = 0u; }
    unsigned mask = 0u;
    for (int byte = 3; byte >= 0; byte--) {
        for (int i = tid; i < 2048; i += 1024) ((unsigned*)hist)[i] = 0u;
        __syncthreads();
        const unsigned prefix = sh_prefix;
        const int wg = (tid >> 5) & 7;
        const int sh = byte << 3;
        for (int t = tid; t < NN; t += 1024) {
            unsigned key = keys[t];
            if ((key & mask) == prefix)
                atomicAdd(&hist[wg][(key >> sh) & 255u], 1u);
        }
        __syncthreads();
        if (tid < 256) {
            unsigned s = 0;
            #pragma unroll
            for (int c = 0; c < 8; c++) s += hist[c][tid];
            hist[0][tid] = s;
        }
        __syncthreads();
        if (tid == 0) {
            int rem = sh_rem;
            unsigned cum = 0;
            int sel = 0;
            for (int bb = 255; bb >= 0; bb--) {
                unsigned c = hist[0][bb];
                if (cum + c >= (unsigned)rem) { sel = bb; sh_rem = rem - (int)cum; break; }
                cum += c;
            }
            sh_prefix = prefix | ((unsigned)sel << sh);
        }
        __syncthreads();
        mask |= (255u << sh);
    }
    if (tid == 0) g_thr[b] = __uint_as_float(sh_prefix);
}

// ---------------- 5) masked sum + final (R1 verbatim) ----------------
__global__ __launch_bounds__(256) void cmask_sum_kernel(const float* __restrict__ soft)
{
    const int b = blockIdx.y, blk = blockIdx.x, tid = threadIdx.x;
    __shared__ float red[8];
    const float thr = g_thr[b];
    const int base = (b << 16) + (blk << 10);
    float s = 0.f;
    #pragma unroll
    for (int t = 0; t < 4; t++) {
        float v = soft[base + (t << 8) + tid];
        if (v >= thr) s += v;
    }
    #pragma unroll
    for (int o = 16; o > 0; o >>= 1) s += __shfl_xor_sync(0xffffffffu, s, o);
    if ((tid & 31) == 0) red[tid >> 5] = s;
    __syncthreads();
    if (tid == 0) {
        float tot = 0.f;
        #pragma unroll
        for (int i = 0; i < 8; i++) tot += red[i];
        g_cpart[(b << 6) + blk] = tot;
    }
}

__global__ void csum_final_kernel() {
    const int b = blockIdx.x, tid = threadIdx.x;   // 64 threads
    __shared__ float r2[2];
    float v = g_cpart[(b << 6) + tid];
    #pragma unroll
    for (int o = 16; o > 0; o >>= 1) v += __shfl_xor_sync(0xffffffffu, v, o);
    if ((tid & 31) == 0) r2[tid >> 5] = v;
    __syncthreads();
    if (tid == 0) g_inv_csum[b] = 1.0f / (r2[0] + r2[1] + 1e-12f);
}

__global__ void final_kernel(const float* __restrict__ soft,
                             float* __restrict__ out_causal, float* __restrict__ out_conf)
{
    int idx = blockIdx.x * 256 + threadIdx.x;
    int b = idx >> 16;
    float v = soft[idx];
    float c = (v >= g_thr[b]) ? v * g_inv_csum[b] : 0.f;
    out_causal[idx] = c;
    out_conf[idx] = 1.f - c;
}

// ---------------- launch ----------------
// 3 init pads keep gemm_kernel at launch position 4 (the ncu-profiled slot).
extern "C" void kernel_launch(void* const* d_in, const int* in_sizes, int n_in,
                              void* d_out, int out_size)
{
    const float* x  = (const float*)d_in[0];
    const float* W1 = (const float*)d_in[1];
    const float* b1 = (const float*)d_in[2];
    const float* W2 = (const float*)d_in[3];
    const float* b2 = (const float*)d_in[4];
    float* out = (float*)d_out;
    float* out_causal = out;
    float* out_conf   = out + BNN;
    float* out_edge   = out + 2 * BNN;
    float* out_soft   = out + 3 * BNN;

    init_kernel<<<1, 32>>>();
    init_kernel<<<1, 32>>>();
    init_kernel<<<1, 32>>>();
    gemm_kernel<<<dim3(8, 32), 64>>>(x, W1, b1);   // launch #4 -> ncu target
    edge_kernel<<<dim3(4, 4, Bsz), 256>>>(W2, b2, out_edge);
    exp_kernel<<<dim3(64, Bsz), 256>>>(out_edge);
    denom_kernel<<<Bsz, 64>>>();
    soft_kernel<<<2048, 256>>>(out_soft);
    select_kernel<<<Bsz, 1024>>>(out_soft);
    cmask_sum_kernel<<<dim3(64, Bsz), 256>>>(out_soft);
    csum_final_kernel<<<Bsz, 64>>>();
    final_kernel<<<2048, 256>>>(out_soft, out_causal, out_conf);
}